// round 11
// baseline (speedup 1.0000x reference)
#include <cuda_runtime.h>
#include <mma.h>
#include <math.h>
#include <stdint.h>

using namespace nvcuda;

#define T_TOKENS 65536
#define D_MODEL  256
#define E_EXPERTS 8
#define F_FF     1024
#define CAP      10240

// ---------------- scratch (same footprint as passing R1/R10) -----------------
__device__ __align__(128) float g_buf[(size_t)E_EXPERTS * CAP * D_MODEL];
__device__ __align__(128) float g_hmid[(size_t)E_EXPERTS * CAP * F_FF];
__device__ int   g_idx[T_TOKENS];
__device__ float g_prb[T_TOKENS];
__device__ int   g_slot_token[E_EXPERTS * CAP];
__device__ float g_slot_prob[E_EXPERTS * CAP];
__device__ int   g_count[E_EXPERTS];

// ---------------- prep kernels (verbatim from passing R1/R10) ----------------
__global__ void zero_kernel(float4* __restrict__ out, int n4) {
    int i = blockIdx.x * blockDim.x + threadIdx.x;
    if (i < n4) out[i] = make_float4(0.f, 0.f, 0.f, 0.f);
}

__global__ void gate_kernel(const float* __restrict__ x,
                            const float* __restrict__ gw,
                            const float* __restrict__ gb) {
    __shared__ float s_gw[D_MODEL * E_EXPERTS];
    int tid = threadIdx.x;
    for (int i = tid; i < D_MODEL * E_EXPERTS; i += 256) s_gw[i] = gw[i];
    __syncthreads();
    int warp = tid >> 5, lane = tid & 31;
    int t = blockIdx.x * 8 + warp;
    const float* xr = x + (size_t)t * D_MODEL;
    float acc[E_EXPERTS];
#pragma unroll
    for (int e = 0; e < E_EXPERTS; e++) acc[e] = 0.f;
#pragma unroll
    for (int j = 0; j < 8; j++) {
        int d = j * 32 + lane;
        float xv = xr[d];
#pragma unroll
        for (int e = 0; e < E_EXPERTS; e++) acc[e] += xv * s_gw[d * E_EXPERTS + e];
    }
#pragma unroll
    for (int o = 16; o > 0; o >>= 1)
#pragma unroll
        for (int e = 0; e < E_EXPERTS; e++)
            acc[e] += __shfl_xor_sync(0xffffffffu, acc[e], o);
    if (lane == 0) {
        float lg[E_EXPERTS], m = -INFINITY; int am = 0;
#pragma unroll
        for (int e = 0; e < E_EXPERTS; e++) {
            lg[e] = acc[e] + gb[e];
            if (lg[e] > m) { m = lg[e]; am = e; }
        }
        float s = 0.f;
#pragma unroll
        for (int e = 0; e < E_EXPERTS; e++) s += expf(lg[e] - m);
        g_idx[t] = am;
        g_prb[t] = 1.0f / s;
    }
}

__global__ void scan_kernel() {
    __shared__ int s[1024][E_EXPERTS];
    int tid = threadIdx.x;
    int base = tid * (T_TOKENS / 1024);
    int cnt[E_EXPERTS];
#pragma unroll
    for (int e = 0; e < E_EXPERTS; e++) cnt[e] = 0;
    for (int i = 0; i < T_TOKENS / 1024; i++) cnt[g_idx[base + i]]++;
#pragma unroll
    for (int e = 0; e < E_EXPERTS; e++) s[tid][e] = cnt[e];
    __syncthreads();
    for (int off = 1; off < 1024; off <<= 1) {
        int v[E_EXPERTS];
        if (tid >= off)
#pragma unroll
            for (int e = 0; e < E_EXPERTS; e++) v[e] = s[tid - off][e];
        __syncthreads();
        if (tid >= off)
#pragma unroll
            for (int e = 0; e < E_EXPERTS; e++) s[tid][e] += v[e];
        __syncthreads();
    }
    int run[E_EXPERTS];
#pragma unroll
    for (int e = 0; e < E_EXPERTS; e++) run[e] = s[tid][e] - cnt[e];
    if (tid == 1023)
#pragma unroll
        for (int e = 0; e < E_EXPERTS; e++) g_count[e] = min(s[1023][e], CAP);
    for (int i = 0; i < T_TOKENS / 1024; i++) {
        int t = base + i;
        int e = g_idx[t];
        int pos = run[e]++;
        if (pos < CAP) {
            int slot = e * CAP + pos;
            g_slot_token[slot] = t;
            g_slot_prob[slot]  = g_prb[t];
        }
    }
}

__global__ void dispatch_kernel(const float* __restrict__ x) {
    int slot = blockIdx.x * 4 + (threadIdx.x >> 6);
    int e = slot / CAP, c = slot % CAP;
    if (c >= g_count[e]) return;
    int t = g_slot_token[slot];
    int i = threadIdx.x & 63;
    const float4* src = (const float4*)(x + (size_t)t * D_MODEL);
    float4* dst = (float4*)(g_buf + (size_t)slot * D_MODEL);
    dst[i] = src[i];
}

// ---------------- GEMM1: hmid = relu(buf @ w1 + b1) — PROVEN fp32 (R10) -------
__global__ __launch_bounds__(256) void gemm1_kernel(const float* __restrict__ w1,
                                                    const float* __restrict__ b1) {
    int e  = blockIdx.z;
    int m0 = blockIdx.y * 128;
    int n0 = blockIdx.x * 128;
    if (m0 >= g_count[e]) return;

    const float* A = g_buf + (size_t)e * CAP * D_MODEL;
    const float* B = w1    + (size_t)e * D_MODEL * F_FF;

    __shared__ float As[16][128];
    __shared__ float Bs[16][128];

    int tid = threadIdx.x;
    int tx = tid & 15, ty = tid >> 4;
    int a_row = tid >> 1,  a_k = (tid & 1) * 8;
    int b_row = tid >> 4,  b_c = (tid & 15) * 8;

    float acc[8][8];
#pragma unroll
    for (int i = 0; i < 8; i++)
#pragma unroll
        for (int j = 0; j < 8; j++) acc[i][j] = 0.f;

    for (int k0 = 0; k0 < D_MODEL; k0 += 16) {
        float4 av0 = *(const float4*)(A + (size_t)(m0 + a_row) * D_MODEL + k0 + a_k);
        float4 av1 = *(const float4*)(A + (size_t)(m0 + a_row) * D_MODEL + k0 + a_k + 4);
        As[a_k + 0][a_row] = av0.x; As[a_k + 1][a_row] = av0.y;
        As[a_k + 2][a_row] = av0.z; As[a_k + 3][a_row] = av0.w;
        As[a_k + 4][a_row] = av1.x; As[a_k + 5][a_row] = av1.y;
        As[a_k + 6][a_row] = av1.z; As[a_k + 7][a_row] = av1.w;
        *(float4*)(&Bs[b_row][b_c]) =
            *(const float4*)(B + (size_t)(k0 + b_row) * F_FF + n0 + b_c);
        *(float4*)(&Bs[b_row][b_c + 4]) =
            *(const float4*)(B + (size_t)(k0 + b_row) * F_FF + n0 + b_c + 4);
        __syncthreads();
#pragma unroll
        for (int kk = 0; kk < 16; kk++) {
            float a[8], b[8];
#pragma unroll
            for (int i = 0; i < 8; i++) a[i] = As[kk][ty + i * 16];
#pragma unroll
            for (int j = 0; j < 8; j++) b[j] = Bs[kk][tx * 8 + j];
#pragma unroll
            for (int i = 0; i < 8; i++)
#pragma unroll
                for (int j = 0; j < 8; j++) acc[i][j] += a[i] * b[j];
        }
        __syncthreads();
    }

    float* Hm = g_hmid + (size_t)e * CAP * F_FF;
    int n = n0 + tx * 8;
    float4 bv0 = *(const float4*)(b1 + e * F_FF + n);
    float4 bv1 = *(const float4*)(b1 + e * F_FF + n + 4);
#pragma unroll
    for (int i = 0; i < 8; i++) {
        int m = m0 + ty + i * 16;
        float4 r0, r1;
        r0.x = fmaxf(acc[i][0] + bv0.x, 0.f); r0.y = fmaxf(acc[i][1] + bv0.y, 0.f);
        r0.z = fmaxf(acc[i][2] + bv0.z, 0.f); r0.w = fmaxf(acc[i][3] + bv0.w, 0.f);
        r1.x = fmaxf(acc[i][4] + bv1.x, 0.f); r1.y = fmaxf(acc[i][5] + bv1.y, 0.f);
        r1.z = fmaxf(acc[i][6] + bv1.z, 0.f); r1.w = fmaxf(acc[i][7] + bv1.w, 0.f);
        *(float4*)(Hm + (size_t)m * F_FF + n)     = r0;
        *(float4*)(Hm + (size_t)m * F_FF + n + 4) = r1;
    }
}

// ---------------- GEMM2 (WMMA tf32, 3-term): y = (hmid @ w2 + b2) * prob ------
// CTA 128m x 64n, 8 warps (4m x 2n), warp 32x32 = 2x2 frags (16x16), K-chunk 16.
__global__ __launch_bounds__(256) void gemm2_wmma(const float* __restrict__ w2,
                                                  const float* __restrict__ b2,
                                                  float* __restrict__ y) {
    __shared__ float sAh[128][16];
    __shared__ float sAl[128][16];
    __shared__ float sBh[16][64];
    __shared__ float sBl[16][64];
    __shared__ __align__(32) float sbuf[8][256];

    int e = blockIdx.z, m0 = blockIdx.y * 128, n0 = blockIdx.x * 64;
    int cnt = g_count[e];
    if (m0 >= cnt) return;
    int tid = threadIdx.x, wid = tid >> 5, lane = tid & 31;
    int wm = (wid >> 1) * 32, wn = (wid & 1) * 32;

    const float* A = g_hmid + (size_t)(e * CAP + m0) * F_FF;
    const float* B = w2 + (size_t)e * F_FF * D_MODEL;

    wmma::fragment<wmma::accumulator, 16, 16, 8, float> acc[2][2];
#pragma unroll
    for (int mi = 0; mi < 2; mi++)
#pragma unroll
        for (int ni = 0; ni < 2; ni++) wmma::fill_fragment(acc[mi][ni], 0.f);

    int arow = tid >> 1, acol = (tid & 1) * 8;
    int brow = tid >> 4, bcol = (tid & 15) * 4;

#pragma unroll 1
    for (int k0 = 0; k0 < F_FF; k0 += 16) {
        // stage A[128][16]: hi = tf32(v), lo = v - hi
        float4 v0 = *(const float4*)(A + (size_t)arow * F_FF + k0 + acol);
        float4 v1 = *(const float4*)(A + (size_t)arow * F_FF + k0 + acol + 4);
#pragma unroll
        for (int j = 0; j < 8; j++) {
            float v = (j < 4) ? (&v0.x)[j] : (&v1.x)[j - 4];
            float h = wmma::__float_to_tf32(v);
            sAh[arow][acol + j] = h;
            sAl[arow][acol + j] = wmma::__float_to_tf32(v - h);
        }
        // stage B[16][64] from w2[k][n]
        float4 bv = *(const float4*)(B + (size_t)(k0 + brow) * D_MODEL + n0 + bcol);
#pragma unroll
        for (int j = 0; j < 4; j++) {
            float v = (&bv.x)[j];
            float h = wmma::__float_to_tf32(v);
            sBh[brow][bcol + j] = h;
            sBl[brow][bcol + j] = wmma::__float_to_tf32(v - h);
        }
        __syncthreads();

#pragma unroll
        for (int ks = 0; ks < 2; ks++) {
            wmma::fragment<wmma::matrix_a, 16, 16, 8, wmma::precision::tf32, wmma::row_major> ah[2], al[2];
            wmma::fragment<wmma::matrix_b, 16, 16, 8, wmma::precision::tf32, wmma::row_major> bh[2], bl[2];
#pragma unroll
            for (int mi = 0; mi < 2; mi++) {
                wmma::load_matrix_sync(ah[mi], &sAh[wm + mi * 16][ks * 8], 16);
                wmma::load_matrix_sync(al[mi], &sAl[wm + mi * 16][ks * 8], 16);
            }
#pragma unroll
            for (int ni = 0; ni < 2; ni++) {
                wmma::load_matrix_sync(bh[ni], &sBh[ks * 8][wn + ni * 16], 64);
                wmma::load_matrix_sync(bl[ni], &sBl[ks * 8][wn + ni * 16], 64);
            }
#pragma unroll
            for (int mi = 0; mi < 2; mi++)
#pragma unroll
                for (int ni = 0; ni < 2; ni++) {
                    wmma::mma_sync(acc[mi][ni], ah[mi], bh[ni], acc[mi][ni]);
                    wmma::mma_sync(acc[mi][ni], ah[mi], bl[ni], acc[mi][ni]);
                    wmma::mma_sync(acc[mi][ni], al[mi], bh[ni], acc[mi][ni]);
                }
        }
        __syncthreads();
    }

    const float* bb = b2 + e * D_MODEL + n0 + wn;
    int r = lane >> 1, cb = (lane & 1) * 8;
#pragma unroll
    for (int mi = 0; mi < 2; mi++)
#pragma unroll
        for (int ni = 0; ni < 2; ni++) {
            wmma::store_matrix_sync(&sbuf[wid][0], acc[mi][ni], 16, wmma::mem_row_major);
            __syncwarp();
            int row = m0 + wm + mi * 16 + r;
            if (row < cnt) {
                int t = g_slot_token[e * CAP + row];
                float p = g_slot_prob[e * CAP + row];
                float* yr = y + (size_t)t * D_MODEL + n0 + wn + ni * 16 + cb;
#pragma unroll
                for (int j = 0; j < 8; j += 2) {
                    float2 v;
                    v.x = (sbuf[wid][r * 16 + cb + j]     + __ldg(bb + ni * 16 + cb + j))     * p;
                    v.y = (sbuf[wid][r * 16 + cb + j + 1] + __ldg(bb + ni * 16 + cb + j + 1)) * p;
                    *(float2*)(yr + j) = v;
                }
            }
            __syncwarp();
        }
}

// ---------------- launch ------------------------------------------------------
extern "C" void kernel_launch(void* const* d_in, const int* in_sizes, int n_in,
                              void* d_out, int out_size) {
    const float* h      = (const float*)d_in[0];
    const float* gate_w = (const float*)d_in[1];
    const float* gate_b = (const float*)d_in[2];
    const float* w1     = (const float*)d_in[3];
    const float* b1     = (const float*)d_in[4];
    const float* w2     = (const float*)d_in[5];
    const float* b2     = (const float*)d_in[6];
    float* out = (float*)d_out;

    int n4 = out_size / 4;
    zero_kernel<<<(n4 + 255) / 256, 256>>>((float4*)out, n4);
    gate_kernel<<<T_TOKENS / 8, 256>>>(h, gate_w, gate_b);
    scan_kernel<<<1, 1024>>>();
    dispatch_kernel<<<E_EXPERTS * CAP / 4, 256>>>(h);
    gemm1_kernel<<<dim3(F_FF / 128, CAP / 128, E_EXPERTS), 256>>>(w1, b1);
    gemm2_wmma<<<dim3(D_MODEL / 64, CAP / 128, E_EXPERTS), 256>>>(w2, b2, out);
}